// round 9
// baseline (speedup 1.0000x reference)
#include <cuda_runtime.h>
#include <math.h>

#define R_MAX_F 6.0f
#define PI_F 3.14159265358979323846f
#define MAX_N 50048
#define MAX_DEG 80

// Static scratch (alloc-free rule). g_count zero at module load; k_gather
// re-zeroes after reading, so every execution starts from zero.
__device__ int g_count[MAX_N];
__device__ float4 g_edata[MAX_N * MAX_DEG];   // 64 MB (ux,uy,uz,r) per edge

// Kernel 1 (fused): blocks [0,NB): coalesced embedding copy (scheduled first,
// pure bandwidth). Blocks [NB,NB+EB): bucket 8 edges/thread; atomics issued
// FIRST (right after idx loads) so dr loads + normalization run under the
// atomic scoreboard and the slot returns are ready by store time.
__global__ void __launch_bounds__(256) k_bucket(const float* __restrict__ dr,
                                                const int* __restrict__ idx,
                                                const int* __restrict__ Z,
                                                const float4* __restrict__ emb4,
                                                float4* __restrict__ out4,
                                                int E, int N, int NB) {
    int b = blockIdx.x;
    int tid = threadIdx.x;

    if (b < NB) {
        // --- Embedding copy: 8 float4 per thread, stride-256 coalesced ---
        int base = b * 2048 + tid;
        long total = (long)N * 32;
#pragma unroll
        for (int k = 0; k < 8; k++) {
            long lin = base + k * 256;
            if (lin < total) {
                int n = (int)(lin >> 5);
                int c = (int)(lin & 31);
                int z = Z[n];
                float4 v = make_float4(0.f, 0.f, 0.f, 0.f);
                if (z != 0) v = emb4[z * 32 + c];
                out4[(size_t)n * 40 + c] = v;
            }
        }
        return;
    }

    // --- Edge bucketing: 8 edges per thread ---
    int t = (b - NB) * 256 + tid;
    int e0 = t * 8;
    if (e0 >= E) return;

    int ii[8], jj[8], slot[8];
    float ex[8], ey[8], ez[8], rr[8];

    if (e0 + 8 <= E) {
        // 1) idx loads
        int4 iv0 = __ldg((const int4*)(idx + e0));
        int4 iv1 = __ldg((const int4*)(idx + e0 + 4));
        int4 jv0 = __ldg((const int4*)(idx + E + e0));
        int4 jv1 = __ldg((const int4*)(idx + E + e0 + 4));
        ii[0]=iv0.x; ii[1]=iv0.y; ii[2]=iv0.z; ii[3]=iv0.w;
        ii[4]=iv1.x; ii[5]=iv1.y; ii[6]=iv1.z; ii[7]=iv1.w;
        jj[0]=jv0.x; jj[1]=jv0.y; jj[2]=jv0.z; jj[3]=jv0.w;
        jj[4]=jv1.x; jj[5]=jv1.y; jj[6]=jv1.z; jj[7]=jv1.w;

        // 2) atomics issued EARLY — everything below hides their latency
#pragma unroll
        for (int u = 0; u < 8; u++)
            slot[u] = (ii[u] != jj[u]) ? atomicAdd(&g_count[ii[u]], 1) : MAX_DEG;

        // 3) dr loads
        const float4* dr4 = (const float4*)dr;
        float4 p0 = __ldg(&dr4[6 * t + 0]);
        float4 p1 = __ldg(&dr4[6 * t + 1]);
        float4 p2 = __ldg(&dr4[6 * t + 2]);
        float4 p3 = __ldg(&dr4[6 * t + 3]);
        float4 p4 = __ldg(&dr4[6 * t + 4]);
        float4 p5 = __ldg(&dr4[6 * t + 5]);
        ex[0]=p0.x; ey[0]=p0.y; ez[0]=p0.z;
        ex[1]=p0.w; ey[1]=p1.x; ez[1]=p1.y;
        ex[2]=p1.z; ey[2]=p1.w; ez[2]=p2.x;
        ex[3]=p2.y; ey[3]=p2.z; ez[3]=p2.w;
        ex[4]=p3.x; ey[4]=p3.y; ez[4]=p3.z;
        ex[5]=p3.w; ey[5]=p4.x; ez[5]=p4.y;
        ex[6]=p4.z; ey[6]=p4.w; ez[6]=p5.x;
        ex[7]=p5.y; ey[7]=p5.z; ez[7]=p5.w;
    } else {
        int m = E - e0; if (m > 8) m = 8;
#pragma unroll
        for (int u = 0; u < 8; u++) {
            if (u < m) { ii[u] = idx[e0 + u]; jj[u] = idx[E + e0 + u]; }
            else       { ii[u] = 0; jj[u] = 0; }
        }
#pragma unroll
        for (int u = 0; u < 8; u++)
            slot[u] = (ii[u] != jj[u]) ? atomicAdd(&g_count[ii[u]], 1) : MAX_DEG;
#pragma unroll
        for (int u = 0; u < 8; u++) {
            if (u < m) {
                ex[u] = dr[3 * (e0 + u) + 0];
                ey[u] = dr[3 * (e0 + u) + 1];
                ez[u] = dr[3 * (e0 + u) + 2];
            } else { ex[u] = 1.f; ey[u] = 0.f; ez[u] = 0.f; }
        }
    }

    // 4) normalization (FMA/MUFU work runs under the atomic scoreboard)
#pragma unroll
    for (int u = 0; u < 8; u++) {
        float d2 = fmaxf(ex[u]*ex[u] + ey[u]*ey[u] + ez[u]*ez[u], 1e-24f);
        float rinv = rsqrtf(d2);
        rr[u] = d2 * rinv;
        ex[u] *= rinv;
        ey[u] *= rinv;
        ez[u] *= rinv;
    }

    // 5) stores — slot[] returns have landed by now
#pragma unroll
    for (int u = 0; u < 8; u++)
        if (slot[u] < MAX_DEG)
            g_edata[ii[u] * MAX_DEG + slot[u]] =
                make_float4(ex[u], ey[u], ez[u], rr[u]);
}

// Per-edge accumulate on normalized payload (ux,uy,uz,r)
__device__ __forceinline__ void edge_accum(float4 v, float* acc, float& nbh) {
    const float s3   = 1.7320508075688772f;
    const float s15  = 3.872983346207417f;
    const float s104 = 0.7905694150420949f;
    const float s64  = 0.6123724356957945f;
    const float s152 = 1.9364916731037085f;

    float ux = v.x, uy = v.y, uz = v.z, r = v.w;

    float s1, c1;
    __sincosf(r * (PI_F / R_MAX_F), &s1, &c1);
    float cut = (r < R_MAX_F) ? 0.5f * (c1 + 1.0f) : 0.0f;
    nbh += cut;

    float ux2 = ux * ux, uy2 = uy * uy, uz2 = uz * uz;
    acc[1]  += uy;
    acc[2]  += uz;
    acc[3]  += ux;
    acc[4]  += s3 * ux * uy;
    acc[5]  += s3 * uy * uz;
    acc[6]  += 0.5f * (3.0f * uz2 - 1.0f);
    acc[7]  += s3 * ux * uz;
    acc[8]  += 0.5f * s3 * (ux2 - uy2);
    acc[9]  += s104 * uy * (3.0f * ux2 - uy2);
    acc[10] += s15 * ux * uy * uz;
    acc[11] += s64 * uy * (5.0f * uz2 - 1.0f);
    acc[12] += 0.5f * uz * (5.0f * uz2 - 3.0f);
    acc[13] += s64 * ux * (5.0f * uz2 - 1.0f);
    acc[14] += s152 * uz * (ux2 - uy2);
    acc[15] += s104 * ux * (ux2 - 3.0f * uy2);

    float pref = __fdividef(cut * 0.5773502691896258f, r);
    float twoc = 2.0f * c1;
    float sk_prev = 0.0f;
    float sk = s1;
#pragma unroll
    for (int m = 0; m < 16; m++) {
        acc[16 + m] += pref * sk;
        float sk_next = twoc * sk - sk_prev;
        sk_prev = sk;
        sk = sk_next;
    }
}

// Kernel 2: 4 threads per node, software-pipelined, quad shfl reduction,
// single 128B store per node.
__global__ void __launch_bounds__(128) k_gather(const int* __restrict__ Z,
                                                float4* __restrict__ out4,
                                                int N) {
    int tid = threadIdx.x;
    int lane = tid & 3;
    int n = blockIdx.x * 32 + (tid >> 2);
    if (n >= N) return;

    int cnt = g_count[n];
    if (lane == 0) g_count[n] = 0;
    if (cnt > MAX_DEG) cnt = MAX_DEG;

    float acc[32];
#pragma unroll
    for (int k = 0; k < 32; k++) acc[k] = 0.0f;
    float nbh = 0.0f;

    const float4* ed = &g_edata[n * MAX_DEG];

    int k = lane;
    bool va = (k < cnt), vb = (k + 4 < cnt);
    float4 a, b;
    if (va) a = __ldg(&ed[k]);
    if (vb) b = __ldg(&ed[k + 4]);
    while (va) {
        int k2 = k + 8;
        bool vc = (k2 < cnt), vd = (k2 + 4 < cnt);
        float4 c, d;
        if (vc) c = __ldg(&ed[k2]);
        if (vd) d = __ldg(&ed[k2 + 4]);
        edge_accum(a, acc, nbh);
        if (vb) edge_accum(b, acc, nbh);
        a = c; b = d; va = vc; vb = vd; k = k2;
    }

#pragma unroll
    for (int off = 2; off >= 1; off >>= 1) {
        nbh += __shfl_down_sync(0xFFFFFFFFu, nbh, off, 4);
#pragma unroll
        for (int q = 1; q < 32; q++)
            acc[q] += __shfl_down_sync(0xFFFFFFFFu, acc[q], off, 4);
    }
    acc[0] = (float)cnt;

    if (lane == 0) {
        float mask = (Z[n] != 0) ? 1.0f : 0.0f;
        float ps = ((nbh > 0.0f) ? 1.0f / nbh : 1.0f) * mask;

        float4* o = out4 + (size_t)n * 40 + 32;
#pragma unroll
        for (int q = 0; q < 4; q++)
            o[q] = make_float4(acc[4 * q] * ps, acc[4 * q + 1] * ps,
                               acc[4 * q + 2] * ps, acc[4 * q + 3] * ps);
#pragma unroll
        for (int q = 4; q < 8; q++)
            o[q] = make_float4(acc[4 * q] * mask, acc[4 * q + 1] * mask,
                               acc[4 * q + 2] * mask, acc[4 * q + 3] * mask);
    }
}

extern "C" void kernel_launch(void* const* d_in, const int* in_sizes, int n_in,
                              void* d_out, int out_size) {
    const float* dr  = (const float*)d_in[0];   // [E,3]
    const int*   Z   = (const int*)d_in[1];     // [N]
    const int*   idx = (const int*)d_in[2];     // [2,E]
    const float* emb = (const float*)d_in[3];   // [119,128]
    float* out = (float*)d_out;                 // [N,160]

    int E = in_sizes[2] / 2;
    int N = in_sizes[1];

    int EB = (E + 8 * 256 - 1) / (8 * 256);
    int NB = (int)(((long)N * 32 + 2047) / 2048);
    k_bucket<<<NB + EB, 256>>>(dr, idx, Z, (const float4*)emb,
                               (float4*)out, E, N, NB);
    k_gather<<<(N + 31) / 32, 128>>>(Z, (float4*)out, N);
}

// round 10
// speedup vs baseline: 1.0839x; 1.0839x over previous
#include <cuda_runtime.h>
#include <math.h>

#define R_MAX_F 6.0f
#define PI_F 3.14159265358979323846f
#define MAX_N 50048
#define MAX_DEG 80

// Static scratch (alloc-free rule). g_count zero at module load; k_gather
// re-zeroes after reading, so every execution starts from zero.
__device__ int g_count[MAX_N];
__device__ float4 g_edata[MAX_N * MAX_DEG];   // 64 MB (ux,uy,uz,r) per edge

// Kernel 1 (fused, R8-proven ordering): blocks [0,EB): bucket 8 edges/thread
// (loads -> normalize -> atomics -> stores). Blocks [EB,EB+NB): emb copy.
__global__ void __launch_bounds__(256) k_bucket(const float* __restrict__ dr,
                                                const int* __restrict__ idx,
                                                const int* __restrict__ Z,
                                                const float4* __restrict__ emb4,
                                                float4* __restrict__ out4,
                                                int E, int N, int EB) {
    int b = blockIdx.x;
    int tid = threadIdx.x;

    if (b >= EB) {
        // --- Embedding copy: 8 float4 per thread, stride-256 coalesced ---
        int base = (b - EB) * 2048 + tid;
        long total = (long)N * 32;
#pragma unroll
        for (int k = 0; k < 8; k++) {
            long lin = base + k * 256;
            if (lin < total) {
                int n = (int)(lin >> 5);
                int c = (int)(lin & 31);
                int z = Z[n];
                float4 v = make_float4(0.f, 0.f, 0.f, 0.f);
                if (z != 0) v = emb4[z * 32 + c];
                out4[(size_t)n * 40 + c] = v;
            }
        }
        return;
    }

    // --- Edge bucketing: 8 edges per thread ---
    int t = b * 256 + tid;
    int e0 = t * 8;
    if (e0 >= E) return;

    int ii[8], jj[8];
    float ex[8], ey[8], ez[8], rr[8];

    if (e0 + 8 <= E) {
        int4 iv0 = __ldg((const int4*)(idx + e0));
        int4 iv1 = __ldg((const int4*)(idx + e0 + 4));
        int4 jv0 = __ldg((const int4*)(idx + E + e0));
        int4 jv1 = __ldg((const int4*)(idx + E + e0 + 4));
        ii[0]=iv0.x; ii[1]=iv0.y; ii[2]=iv0.z; ii[3]=iv0.w;
        ii[4]=iv1.x; ii[5]=iv1.y; ii[6]=iv1.z; ii[7]=iv1.w;
        jj[0]=jv0.x; jj[1]=jv0.y; jj[2]=jv0.z; jj[3]=jv0.w;
        jj[4]=jv1.x; jj[5]=jv1.y; jj[6]=jv1.z; jj[7]=jv1.w;

        const float4* dr4 = (const float4*)dr;
        float4 p0 = __ldg(&dr4[6 * t + 0]);
        float4 p1 = __ldg(&dr4[6 * t + 1]);
        float4 p2 = __ldg(&dr4[6 * t + 2]);
        float4 p3 = __ldg(&dr4[6 * t + 3]);
        float4 p4 = __ldg(&dr4[6 * t + 4]);
        float4 p5 = __ldg(&dr4[6 * t + 5]);
        ex[0]=p0.x; ey[0]=p0.y; ez[0]=p0.z;
        ex[1]=p0.w; ey[1]=p1.x; ez[1]=p1.y;
        ex[2]=p1.z; ey[2]=p1.w; ez[2]=p2.x;
        ex[3]=p2.y; ey[3]=p2.z; ez[3]=p2.w;
        ex[4]=p3.x; ey[4]=p3.y; ez[4]=p3.z;
        ex[5]=p3.w; ey[5]=p4.x; ez[5]=p4.y;
        ex[6]=p4.z; ey[6]=p4.w; ez[6]=p5.x;
        ex[7]=p5.y; ey[7]=p5.z; ez[7]=p5.w;
    } else {
        int m = E - e0; if (m > 8) m = 8;
#pragma unroll
        for (int u = 0; u < 8; u++) {
            if (u < m) {
                ii[u] = idx[e0 + u];
                jj[u] = idx[E + e0 + u];
                ex[u] = dr[3 * (e0 + u) + 0];
                ey[u] = dr[3 * (e0 + u) + 1];
                ez[u] = dr[3 * (e0 + u) + 2];
            } else { ii[u] = 0; jj[u] = 0; ex[u] = 1.f; ey[u] = 0.f; ez[u] = 0.f; }
        }
    }

    // normalize payloads (idle FMA pipes here)
#pragma unroll
    for (int u = 0; u < 8; u++) {
        float d2 = fmaxf(ex[u]*ex[u] + ey[u]*ey[u] + ez[u]*ez[u], 1e-24f);
        float rinv = rsqrtf(d2);
        rr[u] = d2 * rinv;
        ex[u] *= rinv;
        ey[u] *= rinv;
        ez[u] *= rinv;
    }

    int slot[8];
#pragma unroll
    for (int u = 0; u < 8; u++)
        slot[u] = (ii[u] != jj[u]) ? atomicAdd(&g_count[ii[u]], 1) : MAX_DEG;
#pragma unroll
    for (int u = 0; u < 8; u++)
        if (slot[u] < MAX_DEG)
            g_edata[ii[u] * MAX_DEG + slot[u]] =
                make_float4(ex[u], ey[u], ez[u], rr[u]);
}

// Per-edge accumulate — MUFU-free: polynomial cos + sinc, division-free
// radial via S_k = sin(k*theta)/theta Chebyshev recurrence.
__device__ __forceinline__ void edge_accum(float4 v, float* acc, float& nbh) {
    const float s3   = 1.7320508075688772f;
    const float s15  = 3.872983346207417f;
    const float s104 = 0.7905694150420949f;
    const float s64  = 0.6123724356957945f;
    const float s152 = 1.9364916731037085f;

    float ux = v.x, uy = v.y, uz = v.z, r = v.w;

    float theta = r * (PI_F / R_MAX_F);

    // c1 = cos(theta) = -sin(theta - pi/2), deg-11 Taylor on [-pi/2, pi/2]
    float vv = theta - (0.5f * PI_F);
    float w = vv * vv;
    float sv = -2.50521084e-8f;
    sv = fmaf(sv, w,  2.75573192e-6f);
    sv = fmaf(sv, w, -1.98412698e-4f);
    sv = fmaf(sv, w,  8.33333333e-3f);
    sv = fmaf(sv, w, -1.66666667e-1f);
    sv = fmaf(sv, w,  1.0f);
    float c1 = -vv * sv;

    float cut = (r < R_MAX_F) ? fmaf(0.5f, c1, 0.5f) : 0.0f;
    nbh += cut;

    // S1 = sinc(theta), even Taylor deg 13 in theta (x = theta^2)
    float x = theta * theta;
    float S1 = 1.60590438e-10f;
    S1 = fmaf(S1, x, -2.50521084e-8f);
    S1 = fmaf(S1, x,  2.75573192e-6f);
    S1 = fmaf(S1, x, -1.98412698e-4f);
    S1 = fmaf(S1, x,  8.33333333e-3f);
    S1 = fmaf(S1, x, -1.66666667e-1f);
    S1 = fmaf(S1, x,  1.0f);

    float ux2 = ux * ux, uy2 = uy * uy, uz2 = uz * uz;
    acc[1]  += uy;
    acc[2]  += uz;
    acc[3]  += ux;
    acc[4]  += s3 * ux * uy;
    acc[5]  += s3 * uy * uz;
    acc[6]  += 0.5f * (3.0f * uz2 - 1.0f);
    acc[7]  += s3 * ux * uz;
    acc[8]  += 0.5f * s3 * (ux2 - uy2);
    acc[9]  += s104 * uy * (3.0f * ux2 - uy2);
    acc[10] += s15 * ux * uy * uz;
    acc[11] += s64 * uy * (5.0f * uz2 - 1.0f);
    acc[12] += 0.5f * uz * (5.0f * uz2 - 3.0f);
    acc[13] += s64 * ux * (5.0f * uz2 - 1.0f);
    acc[14] += s152 * uz * (ux2 - uy2);
    acc[15] += s104 * ux * (ux2 - 3.0f * uy2);

    // rad_k = cut*sqrt(2/6)*sin(k*theta)/r = pref*S_k, pref = cut*sqrt(2/6)*(pi/6)
    float pref = 0.30229989f * cut;
    float twoc = 2.0f * c1;
    float sk_prev = 0.0f;     // S_0
    float sk = S1;            // S_1
#pragma unroll
    for (int m = 0; m < 16; m++) {
        acc[16 + m] += pref * sk;
        float sk_next = fmaf(twoc, sk, -sk_prev);
        sk_prev = sk;
        sk = sk_next;
    }
}

// Kernel 2: 4 threads per node, software-pipelined, quad shfl reduction,
// single 128B store per node.
__global__ void __launch_bounds__(128) k_gather(const int* __restrict__ Z,
                                                float4* __restrict__ out4,
                                                int N) {
    int tid = threadIdx.x;
    int lane = tid & 3;
    int n = blockIdx.x * 32 + (tid >> 2);
    if (n >= N) return;

    int cnt = g_count[n];
    if (lane == 0) g_count[n] = 0;
    if (cnt > MAX_DEG) cnt = MAX_DEG;

    float acc[32];
#pragma unroll
    for (int k = 0; k < 32; k++) acc[k] = 0.0f;
    float nbh = 0.0f;

    const float4* ed = &g_edata[n * MAX_DEG];

    int k = lane;
    bool va = (k < cnt), vb = (k + 4 < cnt);
    float4 a, b;
    if (va) a = __ldg(&ed[k]);
    if (vb) b = __ldg(&ed[k + 4]);
    while (va) {
        int k2 = k + 8;
        bool vc = (k2 < cnt), vd = (k2 + 4 < cnt);
        float4 c, d;
        if (vc) c = __ldg(&ed[k2]);
        if (vd) d = __ldg(&ed[k2 + 4]);
        edge_accum(a, acc, nbh);
        if (vb) edge_accum(b, acc, nbh);
        a = c; b = d; va = vc; vb = vd; k = k2;
    }

#pragma unroll
    for (int off = 2; off >= 1; off >>= 1) {
        nbh += __shfl_down_sync(0xFFFFFFFFu, nbh, off, 4);
#pragma unroll
        for (int q = 1; q < 32; q++)
            acc[q] += __shfl_down_sync(0xFFFFFFFFu, acc[q], off, 4);
    }
    acc[0] = (float)cnt;

    if (lane == 0) {
        float mask = (Z[n] != 0) ? 1.0f : 0.0f;
        float ps = ((nbh > 0.0f) ? 1.0f / nbh : 1.0f) * mask;

        float4* o = out4 + (size_t)n * 40 + 32;
#pragma unroll
        for (int q = 0; q < 4; q++)
            o[q] = make_float4(acc[4 * q] * ps, acc[4 * q + 1] * ps,
                               acc[4 * q + 2] * ps, acc[4 * q + 3] * ps);
#pragma unroll
        for (int q = 4; q < 8; q++)
            o[q] = make_float4(acc[4 * q] * mask, acc[4 * q + 1] * mask,
                               acc[4 * q + 2] * mask, acc[4 * q + 3] * mask);
    }
}

extern "C" void kernel_launch(void* const* d_in, const int* in_sizes, int n_in,
                              void* d_out, int out_size) {
    const float* dr  = (const float*)d_in[0];   // [E,3]
    const int*   Z   = (const int*)d_in[1];     // [N]
    const int*   idx = (const int*)d_in[2];     // [2,E]
    const float* emb = (const float*)d_in[3];   // [119,128]
    float* out = (float*)d_out;                 // [N,160]

    int E = in_sizes[2] / 2;
    int N = in_sizes[1];

    int EB = (E + 8 * 256 - 1) / (8 * 256);
    int NB = (int)(((long)N * 32 + 2047) / 2048);
    k_bucket<<<EB + NB, 256>>>(dr, idx, Z, (const float4*)emb,
                               (float4*)out, E, N, EB);
    k_gather<<<(N + 31) / 32, 128>>>(Z, (float4*)out, N);
}

// round 11
// speedup vs baseline: 1.1506x; 1.0616x over previous
#include <cuda_runtime.h>
#include <math.h>

#define R_MAX_F 6.0f
#define PI_F 3.14159265358979323846f
#define MAX_N 50048
#define MAX_DEG 80

// Static scratch (alloc-free rule). g_count zero at module load; k_gather
// re-zeroes after reading, so every execution starts from zero.
__device__ int g_count[MAX_N];
__device__ float4 g_edata[MAX_N * MAX_DEG];   // 64 MB (ux,uy,uz,r) per edge

// Kernel 1 (fused): blocks [0,EB): bucket ONE edge per thread (max TLP —
// the scattered atomic + scattered 16B store are wavefront-bound, so more
// threads wins). Blocks [EB,EB+NB): coalesced embedding copy.
__global__ void __launch_bounds__(256) k_bucket(const float* __restrict__ dr,
                                                const int* __restrict__ idx,
                                                const int* __restrict__ Z,
                                                const float4* __restrict__ emb4,
                                                float4* __restrict__ out4,
                                                int E, int N, int EB) {
    int b = blockIdx.x;
    int tid = threadIdx.x;

    if (b >= EB) {
        // --- Embedding copy: 8 float4 per thread, stride-256 coalesced ---
        int base = (b - EB) * 2048 + tid;
        long total = (long)N * 32;
#pragma unroll
        for (int k = 0; k < 8; k++) {
            long lin = base + k * 256;
            if (lin < total) {
                int n = (int)(lin >> 5);
                int c = (int)(lin & 31);
                int z = Z[n];
                float4 v = make_float4(0.f, 0.f, 0.f, 0.f);
                if (z != 0) v = emb4[z * 32 + c];
                out4[(size_t)n * 40 + c] = v;
            }
        }
        return;
    }

    // --- Edge bucketing: one edge per thread ---
    int e = b * 256 + tid;
    if (e >= E) return;
    int i = idx[e];
    int j = idx[E + e];
    if (i == j) return;

    float x = dr[3 * e + 0];
    float y = dr[3 * e + 1];
    float z = dr[3 * e + 2];
    float d2 = fmaxf(x * x + y * y + z * z, 1e-24f);
    float rinv = rsqrtf(d2);
    float r = d2 * rinv;

    int slot = atomicAdd(&g_count[i], 1);
    if (slot < MAX_DEG)
        g_edata[i * MAX_DEG + slot] =
            make_float4(x * rinv, y * rinv, z * rinv, r);
}

// Per-edge accumulate on normalized payload (ux,uy,uz,r) — R8 proven version
__device__ __forceinline__ void edge_accum(float4 v, float* acc, float& nbh) {
    const float s3   = 1.7320508075688772f;
    const float s15  = 3.872983346207417f;
    const float s104 = 0.7905694150420949f;
    const float s64  = 0.6123724356957945f;
    const float s152 = 1.9364916731037085f;

    float ux = v.x, uy = v.y, uz = v.z, r = v.w;

    float s1, c1;
    __sincosf(r * (PI_F / R_MAX_F), &s1, &c1);
    float cut = (r < R_MAX_F) ? 0.5f * (c1 + 1.0f) : 0.0f;
    nbh += cut;

    float ux2 = ux * ux, uy2 = uy * uy, uz2 = uz * uz;
    acc[1]  += uy;
    acc[2]  += uz;
    acc[3]  += ux;
    acc[4]  += s3 * ux * uy;
    acc[5]  += s3 * uy * uz;
    acc[6]  += 0.5f * (3.0f * uz2 - 1.0f);
    acc[7]  += s3 * ux * uz;
    acc[8]  += 0.5f * s3 * (ux2 - uy2);
    acc[9]  += s104 * uy * (3.0f * ux2 - uy2);
    acc[10] += s15 * ux * uy * uz;
    acc[11] += s64 * uy * (5.0f * uz2 - 1.0f);
    acc[12] += 0.5f * uz * (5.0f * uz2 - 3.0f);
    acc[13] += s64 * ux * (5.0f * uz2 - 1.0f);
    acc[14] += s152 * uz * (ux2 - uy2);
    acc[15] += s104 * ux * (ux2 - 3.0f * uy2);

    float pref = __fdividef(cut * 0.5773502691896258f, r);
    float twoc = 2.0f * c1;
    float sk_prev = 0.0f;
    float sk = s1;
#pragma unroll
    for (int m = 0; m < 16; m++) {
        acc[16 + m] += pref * sk;
        float sk_next = twoc * sk - sk_prev;
        sk_prev = sk;
        sk = sk_next;
    }
}

// Kernel 2: 4 threads per node, software-pipelined, quad shfl reduction,
// single 128B store per node. (R8 exact)
__global__ void __launch_bounds__(128) k_gather(const int* __restrict__ Z,
                                                float4* __restrict__ out4,
                                                int N) {
    int tid = threadIdx.x;
    int lane = tid & 3;
    int n = blockIdx.x * 32 + (tid >> 2);
    if (n >= N) return;

    int cnt = g_count[n];
    if (lane == 0) g_count[n] = 0;
    if (cnt > MAX_DEG) cnt = MAX_DEG;

    float acc[32];
#pragma unroll
    for (int k = 0; k < 32; k++) acc[k] = 0.0f;
    float nbh = 0.0f;

    const float4* ed = &g_edata[n * MAX_DEG];

    int k = lane;
    bool va = (k < cnt), vb = (k + 4 < cnt);
    float4 a, b;
    if (va) a = __ldg(&ed[k]);
    if (vb) b = __ldg(&ed[k + 4]);
    while (va) {
        int k2 = k + 8;
        bool vc = (k2 < cnt), vd = (k2 + 4 < cnt);
        float4 c, d;
        if (vc) c = __ldg(&ed[k2]);
        if (vd) d = __ldg(&ed[k2 + 4]);
        edge_accum(a, acc, nbh);
        if (vb) edge_accum(b, acc, nbh);
        a = c; b = d; va = vc; vb = vd; k = k2;
    }

#pragma unroll
    for (int off = 2; off >= 1; off >>= 1) {
        nbh += __shfl_down_sync(0xFFFFFFFFu, nbh, off, 4);
#pragma unroll
        for (int q = 1; q < 32; q++)
            acc[q] += __shfl_down_sync(0xFFFFFFFFu, acc[q], off, 4);
    }
    acc[0] = (float)cnt;

    if (lane == 0) {
        float mask = (Z[n] != 0) ? 1.0f : 0.0f;
        float ps = ((nbh > 0.0f) ? 1.0f / nbh : 1.0f) * mask;

        float4* o = out4 + (size_t)n * 40 + 32;
#pragma unroll
        for (int q = 0; q < 4; q++)
            o[q] = make_float4(acc[4 * q] * ps, acc[4 * q + 1] * ps,
                               acc[4 * q + 2] * ps, acc[4 * q + 3] * ps);
#pragma unroll
        for (int q = 4; q < 8; q++)
            o[q] = make_float4(acc[4 * q] * mask, acc[4 * q + 1] * mask,
                               acc[4 * q + 2] * mask, acc[4 * q + 3] * mask);
    }
}

extern "C" void kernel_launch(void* const* d_in, const int* in_sizes, int n_in,
                              void* d_out, int out_size) {
    const float* dr  = (const float*)d_in[0];   // [E,3]
    const int*   Z   = (const int*)d_in[1];     // [N]
    const int*   idx = (const int*)d_in[2];     // [2,E]
    const float* emb = (const float*)d_in[3];   // [119,128]
    float* out = (float*)d_out;                 // [N,160]

    int E = in_sizes[2] / 2;
    int N = in_sizes[1];

    int EB = (E + 255) / 256;
    int NB = (int)(((long)N * 32 + 2047) / 2048);
    k_bucket<<<EB + NB, 256>>>(dr, idx, Z, (const float4*)emb,
                               (float4*)out, E, N, EB);
    k_gather<<<(N + 31) / 32, 128>>>(Z, (float4*)out, N);
}

// round 12
// speedup vs baseline: 1.1523x; 1.0015x over previous
#include <cuda_runtime.h>
#include <math.h>

#define R_MAX_F 6.0f
#define PI_F 3.14159265358979323846f
#define MAX_N 50048
#define MAX_DEG 64

// Static scratch (alloc-free rule). g_count zero at module load; k_gather
// re-zeroes after reading, so every execution starts from zero.
__device__ int g_count[MAX_N];
__device__ float4 g_edata[MAX_N * MAX_DEG];   // 51 MB (ux,uy,uz,r) per edge

// Kernel 1 (fused): blocks [0,EB): bucket ONE edge per thread (max TLP —
// scattered atomic + scattered 16B store are wavefront-bound).
// Blocks [EB,EB+NB): coalesced embedding copy.
__global__ void __launch_bounds__(256) k_bucket(const float* __restrict__ dr,
                                                const int* __restrict__ idx,
                                                const int* __restrict__ Z,
                                                const float4* __restrict__ emb4,
                                                float4* __restrict__ out4,
                                                int E, int N, int EB) {
    int b = blockIdx.x;
    int tid = threadIdx.x;

    if (b >= EB) {
        // --- Embedding copy: 8 float4 per thread, stride-256 coalesced ---
        int base = (b - EB) * 2048 + tid;
        long total = (long)N * 32;
#pragma unroll
        for (int k = 0; k < 8; k++) {
            long lin = base + k * 256;
            if (lin < total) {
                int n = (int)(lin >> 5);
                int c = (int)(lin & 31);
                int z = Z[n];
                float4 v = make_float4(0.f, 0.f, 0.f, 0.f);
                if (z != 0) v = emb4[z * 32 + c];
                out4[(size_t)n * 40 + c] = v;
            }
        }
        return;
    }

    // --- Edge bucketing: one edge per thread ---
    int e = b * 256 + tid;
    if (e >= E) return;
    int i = idx[e];
    int j = idx[E + e];
    if (i == j) return;

    float x = dr[3 * e + 0];
    float y = dr[3 * e + 1];
    float z = dr[3 * e + 2];
    float d2 = fmaxf(x * x + y * y + z * z, 1e-24f);
    float rinv = rsqrtf(d2);
    float r = d2 * rinv;

    int slot = atomicAdd(&g_count[i], 1);
    if (slot < MAX_DEG)
        g_edata[(i << 6) + slot] =
            make_float4(x * rinv, y * rinv, z * rinv, r);
}

// Per-edge accumulate on normalized payload (ux,uy,uz,r)
__device__ __forceinline__ void edge_accum(float4 v, float* acc, float& nbh) {
    const float s3   = 1.7320508075688772f;
    const float s15  = 3.872983346207417f;
    const float s104 = 0.7905694150420949f;
    const float s64  = 0.6123724356957945f;
    const float s152 = 1.9364916731037085f;

    float ux = v.x, uy = v.y, uz = v.z, r = v.w;

    float s1, c1;
    __sincosf(r * (PI_F / R_MAX_F), &s1, &c1);
    float cut = (r < R_MAX_F) ? 0.5f * (c1 + 1.0f) : 0.0f;
    nbh += cut;

    float ux2 = ux * ux, uy2 = uy * uy, uz2 = uz * uz;
    acc[1]  += uy;
    acc[2]  += uz;
    acc[3]  += ux;
    acc[4]  += s3 * ux * uy;
    acc[5]  += s3 * uy * uz;
    acc[6]  += 0.5f * (3.0f * uz2 - 1.0f);
    acc[7]  += s3 * ux * uz;
    acc[8]  += 0.5f * s3 * (ux2 - uy2);
    acc[9]  += s104 * uy * (3.0f * ux2 - uy2);
    acc[10] += s15 * ux * uy * uz;
    acc[11] += s64 * uy * (5.0f * uz2 - 1.0f);
    acc[12] += 0.5f * uz * (5.0f * uz2 - 3.0f);
    acc[13] += s64 * ux * (5.0f * uz2 - 1.0f);
    acc[14] += s152 * uz * (ux2 - uy2);
    acc[15] += s104 * ux * (ux2 - 3.0f * uy2);

    float pref = __fdividef(cut * 0.5773502691896258f, r);
    float twoc = 2.0f * c1;
    float sk_prev = 0.0f;
    float sk = s1;
#pragma unroll
    for (int m = 0; m < 16; m++) {
        acc[16 + m] += pref * sk;
        float sk_next = twoc * sk - sk_prev;
        sk_prev = sk;
        sk = sk_next;
    }
}

// Kernel 2: 4 threads per node, software-pipelined, quad shfl reduction,
// single 128B store per node.
__global__ void __launch_bounds__(128) k_gather(const int* __restrict__ Z,
                                                float4* __restrict__ out4,
                                                int N) {
    int tid = threadIdx.x;
    int lane = tid & 3;
    int n = blockIdx.x * 32 + (tid >> 2);
    if (n >= N) return;

    int cnt = g_count[n];
    if (lane == 0) g_count[n] = 0;
    if (cnt > MAX_DEG) cnt = MAX_DEG;

    float acc[32];
#pragma unroll
    for (int k = 0; k < 32; k++) acc[k] = 0.0f;
    float nbh = 0.0f;

    const float4* ed = &g_edata[n << 6];

    int k = lane;
    bool va = (k < cnt), vb = (k + 4 < cnt);
    float4 a, b;
    if (va) a = __ldg(&ed[k]);
    if (vb) b = __ldg(&ed[k + 4]);
    while (va) {
        int k2 = k + 8;
        bool vc = (k2 < cnt), vd = (k2 + 4 < cnt);
        float4 c, d;
        if (vc) c = __ldg(&ed[k2]);
        if (vd) d = __ldg(&ed[k2 + 4]);
        edge_accum(a, acc, nbh);
        if (vb) edge_accum(b, acc, nbh);
        a = c; b = d; va = vc; vb = vd; k = k2;
    }

#pragma unroll
    for (int off = 2; off >= 1; off >>= 1) {
        nbh += __shfl_down_sync(0xFFFFFFFFu, nbh, off, 4);
#pragma unroll
        for (int q = 1; q < 32; q++)
            acc[q] += __shfl_down_sync(0xFFFFFFFFu, acc[q], off, 4);
    }
    acc[0] = (float)cnt;

    if (lane == 0) {
        float mask = (Z[n] != 0) ? 1.0f : 0.0f;
        float ps = ((nbh > 0.0f) ? 1.0f / nbh : 1.0f) * mask;

        float4* o = out4 + (size_t)n * 40 + 32;
#pragma unroll
        for (int q = 0; q < 4; q++)
            o[q] = make_float4(acc[4 * q] * ps, acc[4 * q + 1] * ps,
                               acc[4 * q + 2] * ps, acc[4 * q + 3] * ps);
#pragma unroll
        for (int q = 4; q < 8; q++)
            o[q] = make_float4(acc[4 * q] * mask, acc[4 * q + 1] * mask,
                               acc[4 * q + 2] * mask, acc[4 * q + 3] * mask);
    }
}

extern "C" void kernel_launch(void* const* d_in, const int* in_sizes, int n_in,
                              void* d_out, int out_size) {
    const float* dr  = (const float*)d_in[0];   // [E,3]
    const int*   Z   = (const int*)d_in[1];     // [N]
    const int*   idx = (const int*)d_in[2];     // [2,E]
    const float* emb = (const float*)d_in[3];   // [119,128]
    float* out = (float*)d_out;                 // [N,160]

    int E = in_sizes[2] / 2;
    int N = in_sizes[1];

    int EB = (E + 255) / 256;
    int NB = (int)(((long)N * 32 + 2047) / 2048);
    k_bucket<<<EB + NB, 256>>>(dr, idx, Z, (const float4*)emb,
                               (float4*)out, E, N, EB);
    k_gather<<<(N + 31) / 32, 128>>>(Z, (float4*)out, N);
}

// round 13
// speedup vs baseline: 1.1549x; 1.0022x over previous
#include <cuda_runtime.h>
#include <math.h>

#define R_MAX_F 6.0f
#define PI_F 3.14159265358979323846f
#define MAX_N 50048
#define MAX_DEG 64

// Static scratch (alloc-free rule). g_count zero at module load; k_gather
// re-zeroes after reading, so every execution starts from zero.
__device__ int g_count[MAX_N];
__device__ float4 g_edata[MAX_N * MAX_DEG];   // 51 MB (ux,uy,uz,r) per edge

// Kernel 1: bucket ONE edge per thread (max TLP — the scattered atomic +
// scattered 16B store are L1tex-wavefront-bound, so max thread count wins).
// Nothing else in this grid: the emb copy moved to k_gather's grid so it
// stops competing with the bucket's L1tex bottleneck.
__global__ void __launch_bounds__(256) k_bucket(const float* __restrict__ dr,
                                                const int* __restrict__ idx,
                                                int E) {
    int e = blockIdx.x * 256 + threadIdx.x;
    if (e >= E) return;
    int i = idx[e];
    int j = idx[E + e];
    if (i == j) return;

    float x = dr[3 * e + 0];
    float y = dr[3 * e + 1];
    float z = dr[3 * e + 2];
    float d2 = fmaxf(x * x + y * y + z * z, 1e-24f);
    float rinv = rsqrtf(d2);
    float r = d2 * rinv;

    int slot = atomicAdd(&g_count[i], 1);
    if (slot < MAX_DEG)
        g_edata[(i << 6) + slot] =
            make_float4(x * rinv, y * rinv, z * rinv, r);
}

// Per-edge accumulate on normalized payload (ux,uy,uz,r)
__device__ __forceinline__ void edge_accum(float4 v, float* acc, float& nbh) {
    const float s3   = 1.7320508075688772f;
    const float s15  = 3.872983346207417f;
    const float s104 = 0.7905694150420949f;
    const float s64  = 0.6123724356957945f;
    const float s152 = 1.9364916731037085f;

    float ux = v.x, uy = v.y, uz = v.z, r = v.w;

    float s1, c1;
    __sincosf(r * (PI_F / R_MAX_F), &s1, &c1);
    float cut = (r < R_MAX_F) ? 0.5f * (c1 + 1.0f) : 0.0f;
    nbh += cut;

    float ux2 = ux * ux, uy2 = uy * uy, uz2 = uz * uz;
    acc[1]  += uy;
    acc[2]  += uz;
    acc[3]  += ux;
    acc[4]  += s3 * ux * uy;
    acc[5]  += s3 * uy * uz;
    acc[6]  += 0.5f * (3.0f * uz2 - 1.0f);
    acc[7]  += s3 * ux * uz;
    acc[8]  += 0.5f * s3 * (ux2 - uy2);
    acc[9]  += s104 * uy * (3.0f * ux2 - uy2);
    acc[10] += s15 * ux * uy * uz;
    acc[11] += s64 * uy * (5.0f * uz2 - 1.0f);
    acc[12] += 0.5f * uz * (5.0f * uz2 - 3.0f);
    acc[13] += s64 * ux * (5.0f * uz2 - 1.0f);
    acc[14] += s152 * uz * (ux2 - uy2);
    acc[15] += s104 * ux * (ux2 - 3.0f * uy2);

    float pref = __fdividef(cut * 0.5773502691896258f, r);
    float twoc = 2.0f * c1;
    float sk_prev = 0.0f;
    float sk = s1;
#pragma unroll
    for (int m = 0; m < 16; m++) {
        acc[16 + m] += pref * sk;
        float sk_next = twoc * sk - sk_prev;
        sk_prev = sk;
        sk = sk_next;
    }
}

// Kernel 2: blocks [0,GB): 4 threads per node, software-pipelined, quad shfl
// reduction, single 128B store per node. Blocks [GB,GB+NB): coalesced
// embedding copy — overlaps with gather's compute-bound blocks (idle mem pipes).
__global__ void __launch_bounds__(128) k_gather(const int* __restrict__ Z,
                                                const float4* __restrict__ emb4,
                                                float4* __restrict__ out4,
                                                int N, int GB) {
    int tid = threadIdx.x;
    int b = blockIdx.x;

    if (b >= GB) {
        // --- Embedding copy: 16 float4 per thread, stride-128 coalesced ---
        long base = (long)(b - GB) * 2048 + tid;
        long total = (long)N * 32;
#pragma unroll
        for (int k = 0; k < 16; k++) {
            long lin = base + (long)k * 128;
            if (lin < total) {
                int n = (int)(lin >> 5);
                int c = (int)(lin & 31);
                int z = Z[n];
                float4 v = make_float4(0.f, 0.f, 0.f, 0.f);
                if (z != 0) v = emb4[z * 32 + c];
                out4[(size_t)n * 40 + c] = v;
            }
        }
        return;
    }

    int lane = tid & 3;
    int n = b * 32 + (tid >> 2);
    if (n >= N) return;

    int cnt = g_count[n];
    if (lane == 0) g_count[n] = 0;
    if (cnt > MAX_DEG) cnt = MAX_DEG;

    float acc[32];
#pragma unroll
    for (int k = 0; k < 32; k++) acc[k] = 0.0f;
    float nbh = 0.0f;

    const float4* ed = &g_edata[n << 6];

    int k = lane;
    bool va = (k < cnt), vb = (k + 4 < cnt);
    float4 a, b2;
    if (va) a = __ldg(&ed[k]);
    if (vb) b2 = __ldg(&ed[k + 4]);
    while (va) {
        int k2 = k + 8;
        bool vc = (k2 < cnt), vd = (k2 + 4 < cnt);
        float4 c, d;
        if (vc) c = __ldg(&ed[k2]);
        if (vd) d = __ldg(&ed[k2 + 4]);
        edge_accum(a, acc, nbh);
        if (vb) edge_accum(b2, acc, nbh);
        a = c; b2 = d; va = vc; vb = vd; k = k2;
    }

#pragma unroll
    for (int off = 2; off >= 1; off >>= 1) {
        nbh += __shfl_down_sync(0xFFFFFFFFu, nbh, off, 4);
#pragma unroll
        for (int q = 1; q < 32; q++)
            acc[q] += __shfl_down_sync(0xFFFFFFFFu, acc[q], off, 4);
    }
    acc[0] = (float)cnt;

    if (lane == 0) {
        float mask = (Z[n] != 0) ? 1.0f : 0.0f;
        float ps = ((nbh > 0.0f) ? 1.0f / nbh : 1.0f) * mask;

        float4* o = out4 + (size_t)n * 40 + 32;
#pragma unroll
        for (int q = 0; q < 4; q++)
            o[q] = make_float4(acc[4 * q] * ps, acc[4 * q + 1] * ps,
                               acc[4 * q + 2] * ps, acc[4 * q + 3] * ps);
#pragma unroll
        for (int q = 4; q < 8; q++)
            o[q] = make_float4(acc[4 * q] * mask, acc[4 * q + 1] * mask,
                               acc[4 * q + 2] * mask, acc[4 * q + 3] * mask);
    }
}

extern "C" void kernel_launch(void* const* d_in, const int* in_sizes, int n_in,
                              void* d_out, int out_size) {
    const float* dr  = (const float*)d_in[0];   // [E,3]
    const int*   Z   = (const int*)d_in[1];     // [N]
    const int*   idx = (const int*)d_in[2];     // [2,E]
    const float* emb = (const float*)d_in[3];   // [119,128]
    float* out = (float*)d_out;                 // [N,160]

    int E = in_sizes[2] / 2;
    int N = in_sizes[1];

    int EB = (E + 255) / 256;
    k_bucket<<<EB, 256>>>(dr, idx, E);

    int GB = (N + 31) / 32;                              // gather node blocks
    int NB = (int)(((long)N * 32 + 2047) / 2048);        // emb copy blocks
    k_gather<<<GB + NB, 128>>>(Z, (const float4*)emb, (float4*)out, N, GB);
}